// round 3
// baseline (speedup 1.0000x reference)
#include <cuda_runtime.h>
#include <cuda_bf16.h>
#include <cstdint>

#define BB 1024
#define TT 512
#define HH 256
#define NGROUP 16
#define NTHR 256
#define WSTRIDE 264
#define GSTRIDE 132
#define WHI_OFF 0
#define WLO_OFF 67584
#define HHI_OFF 135168
#define HLO_OFF 168960
#define WI_OFF 202752
#define BIAS_OFF 203264
#define SMEM_TOTAL 203776

__device__ float    g_h[2][BB * HH];
__device__ unsigned g_bar[NGROUP];

__device__ __forceinline__ void ldsm4(uint32_t a, uint32_t &r0, uint32_t &r1, uint32_t &r2, uint32_t &r3) {
    asm volatile("ldmatrix.sync.aligned.m8n8.x4.shared.b16 {%0,%1,%2,%3},[%4];"
                 : "=r"(r0), "=r"(r1), "=r"(r2), "=r"(r3) : "r"(a));
}
__device__ __forceinline__ void ldsm2(uint32_t a, uint32_t &r0, uint32_t &r1) {
    asm volatile("ldmatrix.sync.aligned.m8n8.x2.shared.b16 {%0,%1},[%2];"
                 : "=r"(r0), "=r"(r1) : "r"(a));
}
__device__ __forceinline__ void mma_bf16(float *c, uint32_t a0, uint32_t a1, uint32_t a2, uint32_t a3,
                                         uint32_t b0, uint32_t b1) {
    asm volatile("mma.sync.aligned.m16n8k16.row.col.f32.bf16.bf16.f32 "
                 "{%0,%1,%2,%3},{%4,%5,%6,%7},{%8,%9},{%0,%1,%2,%3};"
                 : "+f"(c[0]), "+f"(c[1]), "+f"(c[2]), "+f"(c[3])
                 : "r"(a0), "r"(a1), "r"(a2), "r"(a3), "r"(b0), "r"(b1));
}
__device__ __forceinline__ float fsigmoid(float x) { return 1.0f / (1.0f + __expf(-x)); }

__device__ __forceinline__ void split_store(__nv_bfloat16 *dh, __nv_bfloat16 *dl, float4 v) {
    float f[4] = {v.x, v.y, v.z, v.w};
    __nv_bfloat16 hi[4], lo[4];
#pragma unroll
    for (int e = 0; e < 4; e++) {
        hi[e] = __float2bfloat16(f[e]);
        lo[e] = __float2bfloat16(f[e] - __bfloat162float(hi[e]));
    }
    ((__nv_bfloat162 *)dh)[0] = __halves2bfloat162(hi[0], hi[1]);
    ((__nv_bfloat162 *)dh)[1] = __halves2bfloat162(hi[2], hi[3]);
    ((__nv_bfloat162 *)dl)[0] = __halves2bfloat162(lo[0], lo[1]);
    ((__nv_bfloat162 *)dl)[1] = __halves2bfloat162(lo[2], lo[3]);
}

__global__ void init_kernel() { if (threadIdx.x < NGROUP) g_bar[threadIdx.x] = 0u; }

extern __shared__ char smem_raw[];

__global__ void __launch_bounds__(NTHR, 1)
lstm_kernel(const float *__restrict__ x, const float *__restrict__ W_ih,
            const float *__restrict__ W_hh, const float *__restrict__ b_ih,
            const float *__restrict__ b_hh) {
    __nv_bfloat16 *WHI = (__nv_bfloat16 *)(smem_raw + WHI_OFF);
    __nv_bfloat16 *WLO = (__nv_bfloat16 *)(smem_raw + WLO_OFF);
    __nv_bfloat16 *HHI = (__nv_bfloat16 *)(smem_raw + HHI_OFF);
    __nv_bfloat16 *HLO = (__nv_bfloat16 *)(smem_raw + HLO_OFF);
    float *GATES = (float *)(smem_raw + HHI_OFF);  // alias after MMA
    float *WI    = (float *)(smem_raw + WI_OFF);
    float *BIASS = (float *)(smem_raw + BIAS_OFF);

    const int tid  = threadIdx.x;
    const int grp  = blockIdx.x >> 3;
    const int sl   = blockIdx.x & 7;
    const int lane = tid & 31;
    const int warp = tid >> 5;
    const int wm   = warp >> 2, wn = warp & 3;

    // one-time: W_hh slice (hi/lo split), W_ih, biases
    for (int it = tid; it < 128 * 64; it += NTHR) {
        int j = it >> 6, c4 = it & 63;
        int r = ((j >> 5) << 8) + (sl << 5) + (j & 31);
        float4 v = __ldg((const float4 *)(W_hh + r * HH) + c4);
        split_store(WHI + j * WSTRIDE + c4 * 4, WLO + j * WSTRIDE + c4 * 4, v);
    }
    if (tid < 128) {
        int r = ((tid >> 5) << 8) + (sl << 5) + (tid & 31);
        WI[tid] = W_ih[r];
        BIASS[tid] = b_ih[r] + b_hh[r];
    }
    __syncthreads();

    const int m0 = wm * 32;
    const uint32_t hhi_u = (uint32_t)__cvta_generic_to_shared(HHI);
    const uint32_t hlo_u = (uint32_t)__cvta_generic_to_shared(HLO);
    const uint32_t whi_u = (uint32_t)__cvta_generic_to_shared(WHI);
    const uint32_t wlo_u = (uint32_t)__cvta_generic_to_shared(WLO);
    const uint32_t aOff0 = (uint32_t)((m0 + (lane & 15)) * 528 + ((lane >> 4) * 8) * 2);
    const uint32_t aOff1 = aOff0 + 16 * 528;
    uint32_t bOff[4];
#pragma unroll
    for (int j = 0; j < 4; j++)
        bOff[j] = (uint32_t)((wn * 32 + j * 8 + (lane & 7)) * 528 + (((lane >> 3) & 1) * 8) * 2);

    const int kl = tid & 31, rb = (tid >> 5) * 8;
    const int g8 = lane >> 2, tig = lane & 3;
    float creg[8];
#pragma unroll
    for (int r = 0; r < 8; r++) creg[r] = 0.0f;

    for (int t = 0; t < TT; ++t) {
        const float *rbuf = g_h[t & 1];
        float *wbuf = g_h[(t + 1) & 1];

        if (t > 0) {  // load h tile (64x256) -> hi/lo SMEM
            const float4 *src = (const float4 *)(rbuf + grp * 64 * HH);
#pragma unroll
            for (int r4 = 0; r4 < 16; ++r4) {
                int idx = r4 * NTHR + tid;
                int row = idx >> 6, c4 = idx & 63;
                float4 v = __ldcg(src + idx);
                split_store(HHI + row * WSTRIDE + c4 * 4, HLO + row * WSTRIDE + c4 * 4, v);
            }
        }
        __syncthreads();

        float acc[2][4][4];
#pragma unroll
        for (int i = 0; i < 2; i++)
#pragma unroll
            for (int j = 0; j < 4; j++)
#pragma unroll
                for (int e = 0; e < 4; e++) acc[i][j][e] = 0.0f;

        if (t > 0) {
#pragma unroll 4
            for (int kk = 0; kk < 16; ++kk) {
                const uint32_t kB = (uint32_t)(kk * 32);
                uint32_t ah[2][4], al[2][4], bh[4][2], bl[4][2];
                ldsm4(hhi_u + aOff0 + kB, ah[0][0], ah[0][1], ah[0][2], ah[0][3]);
                ldsm4(hhi_u + aOff1 + kB, ah[1][0], ah[1][1], ah[1][2], ah[1][3]);
                ldsm4(hlo_u + aOff0 + kB, al[0][0], al[0][1], al[0][2], al[0][3]);
                ldsm4(hlo_u + aOff1 + kB, al[1][0], al[1][1], al[1][2], al[1][3]);
#pragma unroll
                for (int j = 0; j < 4; j++) {
                    ldsm2(whi_u + bOff[j] + kB, bh[j][0], bh[j][1]);
                    ldsm2(wlo_u + bOff[j] + kB, bl[j][0], bl[j][1]);
                }
#pragma unroll
                for (int i = 0; i < 2; i++)
#pragma unroll
                    for (int j = 0; j < 4; j++) {
                        mma_bf16(acc[i][j], ah[i][0], ah[i][1], ah[i][2], ah[i][3], bh[j][0], bh[j][1]);
                        mma_bf16(acc[i][j], ah[i][0], ah[i][1], ah[i][2], ah[i][3], bl[j][0], bl[j][1]);
                        mma_bf16(acc[i][j], al[i][0], al[i][1], al[i][2], al[i][3], bh[j][0], bh[j][1]);
                    }
            }
        }
        __syncthreads();  // HHI/HLO reads done; GATES may overwrite

#pragma unroll
        for (int i = 0; i < 2; i++)
#pragma unroll
            for (int j = 0; j < 4; j++) {
                int row = m0 + i * 16 + g8;
                int col = wn * 32 + j * 8 + tig * 2;
                *(float2 *)&GATES[row * GSTRIDE + col] = make_float2(acc[i][j][0], acc[i][j][1]);
                *(float2 *)&GATES[(row + 8) * GSTRIDE + col] = make_float2(acc[i][j][2], acc[i][j][3]);
            }
        __syncthreads();

#pragma unroll
        for (int r = 0; r < 8; r++) {
            int b = rb + r, grow = grp * 64 + b;
            float xv = __ldg(&x[grow * TT + t]);
            float pi = GATES[b * GSTRIDE + kl]      + xv * WI[kl]      + BIASS[kl];
            float pf = GATES[b * GSTRIDE + 32 + kl] + xv * WI[32 + kl] + BIASS[32 + kl];
            float pg = GATES[b * GSTRIDE + 64 + kl] + xv * WI[64 + kl] + BIASS[64 + kl];
            float po = GATES[b * GSTRIDE + 96 + kl] + xv * WI[96 + kl] + BIASS[96 + kl];
            float c = fsigmoid(pf) * creg[r] + fsigmoid(pi) * tanhf(pg);
            creg[r] = c;
            __stcg(&wbuf[grow * HH + sl * 32 + kl], fsigmoid(po) * tanhf(c));
        }

        if (t < TT - 1) {
            __syncthreads();  // all h-writes issued before release
            if (tid == 0) {
                __threadfence();
                atomicAdd(&g_bar[grp], 1u);
                unsigned target = 8u * (unsigned)(t + 1), v;
                do {
                    asm volatile("ld.acquire.gpu.u32 %0,[%1];" : "=r"(v) : "l"(&g_bar[grp]) : "memory");
                } while (v < target);
            }
            __syncthreads();
        }
    }
}

__global__ void final_kernel(const float *__restrict__ W_lin, const float *__restrict__ b_lin,
                             float *__restrict__ out) {
    int b = blockIdx.x * blockDim.x + threadIdx.x;
    if (b < BB) {
        const float *h = g_h[0] + b * HH;  // t=511 wrote buffer (511+1)&1 = 0
        float s = 0.0f;
#pragma unroll 8
        for (int k = 0; k < HH; k++) s += h[k] * W_lin[k];
        out[b] = s + b_lin[0];
    }
}

extern "C" void kernel_launch(void *const *d_in, const int *in_sizes, int n_in,
                              void *d_out, int out_size) {
    (void)in_sizes; (void)n_in; (void)out_size;
    const float *x     = (const float *)d_in[0];
    const float *W_ih  = (const float *)d_in[1];
    const float *W_hh  = (const float *)d_in[2];
    const float *b_ih  = (const float *)d_in[3];
    const float *b_hh  = (const float *)d_in[4];
    const float *W_lin = (const float *)d_in[5];
    const float *b_lin = (const float *)d_in[6];
    float *out = (float *)d_out;

    static bool attr_set = false;
    if (!attr_set) {
        cudaFuncSetAttribute(lstm_kernel, cudaFuncAttributeMaxDynamicSharedMemorySize, SMEM_TOTAL);
        attr_set = true;
    }
    init_kernel<<<1, 32>>>();
    lstm_kernel<<<128, NTHR, SMEM_TOTAL>>>(x, W_ih, W_hh, b_ih, b_hh);
    final_kernel<<<4, 256>>>(W_lin, b_lin, out);
}

// round 4
// speedup vs baseline: 1.1320x; 1.1320x over previous
#include <cuda_runtime.h>
#include <cuda_bf16.h>
#include <cstdint>

#define BB 1024
#define TT 512
#define HH 256
#define NTHR 256
#define WSTRIDE 264          // bf16 elems per SMEM row (K=256 + 8 pad) -> 528 B
#define WHI_OFF 0            // 128*528 = 67584
#define WLO_OFF 67584
#define HHI_OFF 135168       // 64*528 = 33792
#define HLO_OFF 168960
#define WI_OFF  202752       // 128 floats
#define BIAS_OFF 203264      // 128 floats
#define SMEM_TOTAL 203776

// persistent state: h as producer-split bf16 hi/lo, and rotating barrier ring
__device__ __nv_bfloat16 g_hhi[BB * HH];
__device__ __nv_bfloat16 g_hlo[BB * HH];
__device__ unsigned g_bar[16][512];   // zero-initialized at module load; self-cleaning

__device__ __forceinline__ void ldsm4(uint32_t a, uint32_t &r0, uint32_t &r1, uint32_t &r2, uint32_t &r3) {
    asm volatile("ldmatrix.sync.aligned.m8n8.x4.shared.b16 {%0,%1,%2,%3},[%4];"
                 : "=r"(r0), "=r"(r1), "=r"(r2), "=r"(r3) : "r"(a));
}
__device__ __forceinline__ void ldsm2(uint32_t a, uint32_t &r0, uint32_t &r1) {
    asm volatile("ldmatrix.sync.aligned.m8n8.x2.shared.b16 {%0,%1},[%2];"
                 : "=r"(r0), "=r"(r1) : "r"(a));
}
__device__ __forceinline__ void mma_bf16(float *c, uint32_t a0, uint32_t a1, uint32_t a2, uint32_t a3,
                                         uint32_t b0, uint32_t b1) {
    asm volatile("mma.sync.aligned.m16n8k16.row.col.f32.bf16.bf16.f32 "
                 "{%0,%1,%2,%3},{%4,%5,%6,%7},{%8,%9},{%0,%1,%2,%3};"
                 : "+f"(c[0]), "+f"(c[1]), "+f"(c[2]), "+f"(c[3])
                 : "r"(a0), "r"(a1), "r"(a2), "r"(a3), "r"(b0), "r"(b1));
}
__device__ __forceinline__ void cpasync16(uint32_t dst, const void *src) {
    asm volatile("cp.async.cg.shared.global [%0],[%1],16;" :: "r"(dst), "l"(src));
}
__device__ __forceinline__ float fsigmoid(float x) {
    return __fdividef(1.0f, 1.0f + __expf(-x));
}
__device__ __forceinline__ float ftanh(float x) {
    float e = __expf(2.0f * x);
    return 1.0f - __fdividef(2.0f, e + 1.0f);
}

extern __shared__ char smem_raw[];

__global__ void __launch_bounds__(NTHR, 1)
lstm_kernel(const float *__restrict__ x, const float *__restrict__ W_ih,
            const float *__restrict__ W_hh, const float *__restrict__ b_ih,
            const float *__restrict__ b_hh, const float *__restrict__ W_lin,
            const float *__restrict__ b_lin, float *__restrict__ out) {
    __nv_bfloat16 *WHI = (__nv_bfloat16 *)(smem_raw + WHI_OFF);
    __nv_bfloat16 *WLO = (__nv_bfloat16 *)(smem_raw + WLO_OFF);
    float *WI    = (float *)(smem_raw + WI_OFF);
    float *BIASS = (float *)(smem_raw + BIAS_OFF);

    const int tid  = threadIdx.x;
    const int grp  = blockIdx.x >> 3;   // batch group 0..15 (64 rows each)
    const int sl   = blockIdx.x & 7;    // hidden slice 0..7 (32 units each)
    const int lane = tid & 31;
    const int warp = tid >> 5;
    const int wm   = warp >> 2, wn = warp & 3;

    // ---- one-time: W_hh slice, unit-interleaved rows j = 4*unit + gate ----
    // global gate row r = gate*256 + sl*32 + unit  =>  r = ((j&3)<<8)+(sl<<5)+(j>>2)
    for (int it = tid; it < 128 * 64; it += NTHR) {
        int j = it >> 6, c4 = it & 63;
        int r = ((j & 3) << 8) + (sl << 5) + (j >> 2);
        float4 v = __ldg((const float4 *)(W_hh + r * HH) + c4);
        float f[4] = {v.x, v.y, v.z, v.w};
        __nv_bfloat16 hi[4], lo[4];
#pragma unroll
        for (int e = 0; e < 4; e++) {
            hi[e] = __float2bfloat16(f[e]);
            lo[e] = __float2bfloat16(f[e] - __bfloat162float(hi[e]));
        }
        __nv_bfloat162 *dh = (__nv_bfloat162 *)(WHI + j * WSTRIDE + c4 * 4);
        __nv_bfloat162 *dl = (__nv_bfloat162 *)(WLO + j * WSTRIDE + c4 * 4);
        dh[0] = __halves2bfloat162(hi[0], hi[1]);
        dh[1] = __halves2bfloat162(hi[2], hi[3]);
        dl[0] = __halves2bfloat162(lo[0], lo[1]);
        dl[1] = __halves2bfloat162(lo[2], lo[3]);
    }
    if (tid < 128) {
        int r = ((tid & 3) << 8) + (sl << 5) + (tid >> 2);
        WI[tid]    = W_ih[r];
        BIASS[tid] = b_ih[r] + b_hh[r];
    }
    __syncthreads();

    // ldmatrix byte offsets
    const int m0 = wm * 32;
    const uint32_t hhi_u = (uint32_t)__cvta_generic_to_shared(smem_raw + HHI_OFF);
    const uint32_t hlo_u = (uint32_t)__cvta_generic_to_shared(smem_raw + HLO_OFF);
    const uint32_t whi_u = (uint32_t)__cvta_generic_to_shared(WHI);
    const uint32_t wlo_u = (uint32_t)__cvta_generic_to_shared(WLO);
    const uint32_t aOff0 = (uint32_t)((m0 + (lane & 15)) * 528 + ((lane >> 4) * 8) * 2);
    const uint32_t aOff1 = aOff0 + 16 * 528;
    uint32_t bOff[4];
#pragma unroll
    for (int j = 0; j < 4; j++)
        bOff[j] = (uint32_t)((wn * 32 + j * 8 + (lane & 7)) * 528 + (((lane >> 3) & 1) * 8) * 2);

    // epilogue mapping: lane pair exchange; thread owns 1 row x 1 unit per (i,j)
    const int p = lane & 1, q = lane >> 2;
    const int rloc0 = m0 + q + 8 * p;          // + 16*i
    int hcol[4];                                // global hidden index per j
#pragma unroll
    for (int j = 0; j < 4; j++) hcol[j] = sl * 32 + wn * 8 + 2 * j + ((lane & 3) >> 1);

    float creg[2][4];
#pragma unroll
    for (int i = 0; i < 2; i++)
#pragma unroll
        for (int j = 0; j < 4; j++) creg[i][j] = 0.0f;

    unsigned *barg = g_bar[grp];

    for (int t = 0; t < TT; ++t) {
        // ---- load h tile (hi/lo bf16, 64x256 each) straight into SMEM ----
        if (t > 0) {
            const __nv_bfloat16 *shi = g_hhi + grp * 64 * HH;
            const __nv_bfloat16 *slo = g_hlo + grp * 64 * HH;
#pragma unroll
            for (int k = 0; k < 8; ++k) {
                int g = k * NTHR + tid;          // 16B chunk id, 2048 total
                uint32_t off = (uint32_t)((g >> 5) * 528 + (g & 31) * 16);
                cpasync16(hhi_u + off, shi + g * 8);
                cpasync16(hlo_u + off, slo + g * 8);
            }
            asm volatile("cp.async.commit_group;");
            asm volatile("cp.async.wait_group 0;");
        }
        __syncthreads();

        float acc[2][4][4];
#pragma unroll
        for (int i = 0; i < 2; i++)
#pragma unroll
            for (int j = 0; j < 4; j++)
#pragma unroll
                for (int e = 0; e < 4; e++) acc[i][j][e] = 0.0f;

        if (t > 0) {
#pragma unroll 4
            for (int kk = 0; kk < 16; ++kk) {
                const uint32_t kB = (uint32_t)(kk * 32);
                uint32_t ah[2][4], al[2][4], bh[4][2], bl[4][2];
                ldsm4(hhi_u + aOff0 + kB, ah[0][0], ah[0][1], ah[0][2], ah[0][3]);
                ldsm4(hhi_u + aOff1 + kB, ah[1][0], ah[1][1], ah[1][2], ah[1][3]);
                ldsm4(hlo_u + aOff0 + kB, al[0][0], al[0][1], al[0][2], al[0][3]);
                ldsm4(hlo_u + aOff1 + kB, al[1][0], al[1][1], al[1][2], al[1][3]);
#pragma unroll
                for (int j = 0; j < 4; j++) {
                    ldsm2(whi_u + bOff[j] + kB, bh[j][0], bh[j][1]);
                    ldsm2(wlo_u + bOff[j] + kB, bl[j][0], bl[j][1]);
                }
#pragma unroll
                for (int i = 0; i < 2; i++)
#pragma unroll
                    for (int j = 0; j < 4; j++) {
                        mma_bf16(acc[i][j], ah[i][0], ah[i][1], ah[i][2], ah[i][3], bh[j][0], bh[j][1]);
                        mma_bf16(acc[i][j], ah[i][0], ah[i][1], ah[i][2], ah[i][3], bl[j][0], bl[j][1]);
                        mma_bf16(acc[i][j], al[i][0], al[i][1], al[i][2], al[i][3], bh[j][0], bh[j][1]);
                    }
            }
        }

        // ---- in-register epilogue: pair exchange, activations, c update ----
#pragma unroll
        for (int i = 0; i < 2; i++) {
            int grow = grp * 64 + rloc0 + 16 * i;
            float xv = __ldg(&x[grow * TT + t]);
#pragma unroll
            for (int j = 0; j < 4; j++) {
                float a0 = acc[i][j][0], a1 = acc[i][j][1], a2 = acc[i][j][2], a3 = acc[i][j][3];
                float s1 = p ? a0 : a2;
                float r1 = __shfl_xor_sync(0xFFFFFFFFu, s1, 1);
                float s2 = p ? a1 : a3;
                float r2 = __shfl_xor_sync(0xFFFFFFFFu, s2, 1);
                float gi = p ? r1 : a0;
                float gf = p ? r2 : a1;
                float gg = p ? a2 : r1;
                float go = p ? a3 : r2;
                int u4 = (hcol[j] - sl * 32) * 4;   // SMEM row base 4*unit
                float4 wi4 = *(const float4 *)&WI[u4];
                float4 bi4 = *(const float4 *)&BIASS[u4];
                gi += xv * wi4.x + bi4.x;
                gf += xv * wi4.y + bi4.y;
                gg += xv * wi4.z + bi4.z;
                go += xv * wi4.w + bi4.w;
                float cc = fsigmoid(gf) * creg[i][j] + fsigmoid(gi) * ftanh(gg);
                creg[i][j] = cc;
                float h = fsigmoid(go) * ftanh(cc);
                __nv_bfloat16 hh = __float2bfloat16(h);
                __nv_bfloat16 hl = __float2bfloat16(h - __bfloat162float(hh));
                int gidx = grow * HH + hcol[j];
                g_hhi[gidx] = hh;
                g_hlo[gidx] = hl;
            }
        }

        // ---- group barrier (rotating self-cleaning counters) ----
        __syncthreads();
        if (tid == 0) {
            if (sl == 0) {
                unsigned *rst = &barg[(t + 448) & 511];
                asm volatile("st.relaxed.gpu.global.u32 [%0],%1;" :: "l"(rst), "r"(0u) : "memory");
            }
            asm volatile("red.release.gpu.global.add.u32 [%0],%1;" :: "l"(&barg[t]), "r"(1u) : "memory");
            unsigned v;
            do {
                asm volatile("ld.acquire.gpu.u32 %0,[%1];" : "=r"(v) : "l"(&barg[t]) : "memory");
            } while (v < 8u);
        }
        __syncthreads();
    }

    // ---- fused final projection: this CTA outputs rows grp*64 + sl*8 .. +7 ----
    {
        int b = grp * 64 + sl * 8 + (tid >> 5);
        const __nv_bfloat16 *hh = g_hhi + b * HH;
        const __nv_bfloat16 *hl = g_hlo + b * HH;
        float s = 0.0f;
#pragma unroll
        for (int k = lane; k < HH; k += 32) {
            float hv = __bfloat162float(__ldcg(&hh[k])) + __bfloat162float(__ldcg(&hl[k]));
            s += hv * __ldg(&W_lin[k]);
        }
#pragma unroll
        for (int o = 16; o > 0; o >>= 1) s += __shfl_xor_sync(0xFFFFFFFFu, s, o);
        if (lane == 0) out[b] = s + __ldg(&b_lin[0]);
    }
}

extern "C" void kernel_launch(void *const *d_in, const int *in_sizes, int n_in,
                              void *d_out, int out_size) {
    (void)in_sizes; (void)n_in; (void)out_size;
    const float *x     = (const float *)d_in[0];
    const float *W_ih  = (const float *)d_in[1];
    const float *W_hh  = (const float *)d_in[2];
    const float *b_ih  = (const float *)d_in[3];
    const float *b_hh  = (const float *)d_in[4];
    const float *W_lin = (const float *)d_in[5];
    const float *b_lin = (const float *)d_in[6];
    float *out = (float *)d_out;

    static bool attr_set = false;
    if (!attr_set) {
        cudaFuncSetAttribute(lstm_kernel, cudaFuncAttributeMaxDynamicSharedMemorySize, SMEM_TOTAL);
        attr_set = true;
    }
    lstm_kernel<<<128, NTHR, SMEM_TOTAL>>>(x, W_ih, W_hh, b_ih, b_hh, W_lin, b_lin, out);
}